// round 14
// baseline (speedup 1.0000x reference)
#include <cuda_runtime.h>
#include <cuda_fp16.h>
#include <cstdint>

// GatedFusion via mma.sync f16 (m16n8k16, fp32 accum).
// R14 = R13 champion (64x64 warp tiles, 4 warps/CTA, 3-stage smem,
// LDG->compute->STS->one-sync, all-fp16 staging, half-blend epilogue) with
// gate+out MERGED into one kernel: out-tiles spin on per-m-block flags so
// they fill the gate grid's tail wave (896 CTAs / 296 slots = 3.03 waves
// left ~40us of idle slots). Mainloop untouched (R8/9/11/12 all regressed).
// Live math (softmax over singleton axis == 1 -> word/topk branch dead):
//   gate  = sigmoid([time|text] @ gate_w^T + gate_b)   (M=16384, N=896, K=1792)
//   fused = gate*time + (1-gate)*text
//   out   = fused @ out_w^T + out_b                    (M=16384, N=896, K=896)

#define M_TOT 16384
#define D_DIM 896
#define K1    1792

#define BM 128
#define BN 128
#define BK 32
#define THREADS 128
#define STAGES 3
#define AB_OFF (STAGES * 512)                 // uint4 entries: B region offset
#define SMEM_BYTES (2 * STAGES * 512 * 16)    // 48 KB -> 2 CTAs/SM

#define MBLOCKS (M_TOT / BM)                  // 128
#define NBLOCKS (D_DIM / BN)                  // 7
#define GATE_CTAS (MBLOCKS * NBLOCKS)         // 896

static __device__ __half g_tf_h[(size_t)M_TOT * D_DIM];
static __device__ __half g_xf_h[(size_t)M_TOT * D_DIM];
static __device__ __half g_gw_h[(size_t)D_DIM * K1];
static __device__ __half g_ow_h[(size_t)D_DIM * D_DIM];
static __device__ __half g_fused[(size_t)M_TOT * D_DIM];
static __device__ int    g_flags[MBLOCKS];

// ---------------- small helpers ---------------------------------------------
__device__ __forceinline__ void ldm_x4(uint32_t* r, uint32_t addr) {
    asm volatile("ldmatrix.sync.aligned.m8n8.x4.shared.b16 {%0,%1,%2,%3}, [%4];"
                 : "=r"(r[0]), "=r"(r[1]), "=r"(r[2]), "=r"(r[3]) : "r"(addr));
}
__device__ __forceinline__ void mma_f16(float* c, const uint32_t* a, const uint32_t* b) {
    asm volatile(
        "mma.sync.aligned.m16n8k16.row.col.f32.f16.f16.f32 "
        "{%0,%1,%2,%3}, {%4,%5,%6,%7}, {%8,%9}, {%0,%1,%2,%3};"
        : "+f"(c[0]), "+f"(c[1]), "+f"(c[2]), "+f"(c[3])
        : "r"(a[0]), "r"(a[1]), "r"(a[2]), "r"(a[3]), "r"(b[0]), "r"(b[1]));
}

// ---------------- fused fp32 -> fp16 pre-convert + flag reset ----------------
#define N_ACT ((size_t)M_TOT * D_DIM)
#define N_GW  ((size_t)D_DIM * K1)
#define N_OW  ((size_t)D_DIM * D_DIM)
__global__ void k_f2h_all(const float* __restrict__ tf, const float* __restrict__ xf,
                          const float* __restrict__ gw, const float* __restrict__ ow) {
    if (blockIdx.x == 0 && threadIdx.x < MBLOCKS) g_flags[threadIdx.x] = 0;
    const size_t tot = (2 * N_ACT + N_GW + N_OW) / 4;
    for (size_t g = blockIdx.x * blockDim.x + threadIdx.x; g < tot;
         g += (size_t)gridDim.x * blockDim.x) {
        const float* src; __half* dst; size_t i = g * 4;
        if (i < N_ACT) {
            src = tf + i; dst = g_tf_h + i;
        } else if (i < 2 * N_ACT) {
            src = xf + (i - N_ACT); dst = g_xf_h + (i - N_ACT);
        } else if (i < 2 * N_ACT + N_GW) {
            src = gw + (i - 2 * N_ACT); dst = g_gw_h + (i - 2 * N_ACT);
        } else {
            src = ow + (i - 2 * N_ACT - N_GW); dst = g_ow_h + (i - 2 * N_ACT - N_GW);
        }
        float4 v = *reinterpret_cast<const float4*>(src);
        __half2 hh[2] = {__floats2half2_rn(v.x, v.y), __floats2half2_rn(v.z, v.w)};
        *reinterpret_cast<uint2*>(dst) = *reinterpret_cast<const uint2*>(hh);
    }
}

// ---------------- staging: LDG.128 -> regs -> swizzled STS.128 ---------------
// Tile = 128 rows x 32 k (half) for A and B. 16B entries:
//   entry(slab,row) = slab*128 + (row ^ (slab*2)), slab = k8/8 in {0..3}
// 128 threads: row32 = tid>>2 (0..31), slab = tid&3; u<4 covers 128 rows.
__device__ __forceinline__ void ldg_pair(uint4 (&ra)[4], uint4 (&rb)[4],
                                         const __half* __restrict__ A, int ldA,
                                         int m0, int kA,
                                         const __half* __restrict__ B, int ldB,
                                         int n0, int kB, int row32, int slab) {
#pragma unroll
    for (int u = 0; u < 4; u++) {
        const int row = row32 + u * 32;
        ra[u] = *reinterpret_cast<const uint4*>(&A[(size_t)(m0 + row) * ldA + kA + slab * 8]);
        rb[u] = *reinterpret_cast<const uint4*>(&B[(size_t)(n0 + row) * ldB + kB + slab * 8]);
    }
}
__device__ __forceinline__ void sts_pair(uint4* sm, int stage, const uint4 (&ra)[4],
                                         const uint4 (&rb)[4], int row32, int slab) {
#pragma unroll
    for (int u = 0; u < 4; u++) {
        const int row = row32 + u * 32;
        const int e = stage * 512 + slab * 128 + (row ^ (slab * 2));
        sm[e] = ra[u];
        sm[AB_OFF + e] = rb[u];
    }
}

// ---------------- compute: warp tile 64x64, mi=4 x ni=8, m16n8k16 ------------
#define GEMM_COMPUTE(cur)                                                         \
    _Pragma("unroll")                                                             \
    for (int ks = 0; ks < 2; ks++) {                                              \
        uint32_t af[4][4], bf[8][2];                                              \
        _Pragma("unroll")                                                         \
        for (int mi = 0; mi < 4; mi++) {                                          \
            const int slab = ks * 2 + a_kh;                                       \
            const int row = wm * 64 + mi * 16 + a_row;                            \
            ldm_x4(af[mi], sbase +                                                \
                   (uint32_t)((cur) * 512 + slab * 128 + (row ^ (slab * 2))) * 16); \
        }                                                                         \
        _Pragma("unroll")                                                         \
        for (int np = 0; np < 4; np++) {                                          \
            const int slab = ks * 2 + b_kh;                                       \
            const int nrow = wn * 64 + np * 16 + b_row;                           \
            uint32_t t[4];                                                        \
            ldm_x4(t, sbase + (uint32_t)AB_OFF * 16 +                             \
                   (uint32_t)((cur) * 512 + slab * 128 + (nrow ^ (slab * 2))) * 16); \
            bf[np * 2][0] = t[0]; bf[np * 2][1] = t[1];                           \
            bf[np * 2 + 1][0] = t[2]; bf[np * 2 + 1][1] = t[3];                   \
        }                                                                         \
        _Pragma("unroll")                                                         \
        for (int mi = 0; mi < 4; mi++)                                            \
            _Pragma("unroll")                                                     \
            for (int ni = 0; ni < 8; ni++)                                        \
                mma_f16(acc[mi][ni], af[mi], bf[ni]);                             \
    }

#define GEMM_PREAMBLE_VARS                                                        \
    const uint32_t sbase = (uint32_t)__cvta_generic_to_shared(smem_dyn);          \
    const int tid  = threadIdx.x;                                                 \
    const int wid  = tid >> 5;                                                    \
    const int lane = tid & 31;                                                    \
    const int qrow = lane >> 2;                                                   \
    const int qk   = lane & 3;                                                    \
    const int wm   = wid & 1;                                                     \
    const int wn   = wid >> 1;                                                    \
    const int row32 = tid >> 2;                                                   \
    const int slabL = tid & 3;                                                    \
    const int a_row = lane & 15;                                                  \
    const int a_kh  = lane >> 4;                                                  \
    const int b_row = (lane & 7) + ((lane >> 4) << 3);                            \
    const int b_kh  = (lane >> 3) & 1;                                            \
    float acc[4][8][4];                                                           \
    _Pragma("unroll")                                                             \
    for (int mi = 0; mi < 4; mi++)                                                \
        _Pragma("unroll")                                                         \
        for (int ni = 0; ni < 8; ni++)                                            \
            _Pragma("unroll")                                                     \
            for (int t = 0; t < 4; t++) acc[mi][ni][t] = 0.f;

// R7 pipeline: 3-stage, one sync per tile.
//   iter kt: LDG(kt+2) -> compute(kt, slot kt%3) -> STS(kt+2 into (kt+2)%3 ==
//   (kt-1)%3, whose compute finished before the previous sync) -> sync.
#define GEMM_MAINLOOP(NT, SRC_A, LD_A, K_A, SRC_B, LD_B)                          \
    {                                                                             \
        uint4 ra[4], rb[4];                                                       \
        ldg_pair(ra, rb, SRC_A(0), LD_A, m0, K_A(0), SRC_B, LD_B, n0, 0, row32, slabL); \
        sts_pair(smem_dyn, 0, ra, rb, row32, slabL);                              \
        ldg_pair(ra, rb, SRC_A(BK), LD_A, m0, K_A(BK), SRC_B, LD_B, n0, BK, row32, slabL); \
        sts_pair(smem_dyn, 1, ra, rb, row32, slabL);                              \
        __syncthreads();                                                          \
        for (int kt = 0; kt < (NT); kt++) {                                       \
            const int kn = kt + 2;                                                \
            if (kn < (NT)) {                                                      \
                const int kb = kn * BK;                                           \
                ldg_pair(ra, rb, SRC_A(kb), LD_A, m0, K_A(kb), SRC_B, LD_B, n0, kb, row32, slabL); \
            }                                                                     \
            GEMM_COMPUTE(kt % STAGES)                                             \
            if (kn < (NT)) sts_pair(smem_dyn, kn % STAGES, ra, rb, row32, slabL); \
            __syncthreads();                                                      \
        }                                                                         \
    }

#define GATE_SRC(kb) ((kb) < D_DIM ? g_tf_h : g_xf_h)
#define GATE_K(kb)   ((kb) < D_DIM ? (kb) : (kb) - D_DIM)
#define ID_SRC(kb)   (g_fused)
#define ID_K(kb)     (kb)

// ============================================================================
// Merged kernel: bids [0,896) gate tiles; bids [896,1792) out tiles that
// spin on g_flags[mblock] (7 gate n-tiles per m-block) before their mainloop.
// CTA slots are granted in bid order -> all gate CTAs issue before any out
// CTA -> no deadlock; out CTAs fill the gate grid's tail-wave idle slots.
// ============================================================================
__global__ void __launch_bounds__(THREADS, 2)
k_gatedfusion(const float* __restrict__ gb, const float* __restrict__ ob,
              float* __restrict__ out)
{
    extern __shared__ uint4 smem_dyn[];
    const int bid = blockIdx.x;

    if (bid < GATE_CTAS) {
        // ---------------- gate tile ----------------
        const int mb = bid / NBLOCKS;
        const int m0 = mb * BM;
        const int n0 = (bid % NBLOCKS) * BN;
        GEMM_PREAMBLE_VARS
        GEMM_MAINLOOP(K1 / BK, GATE_SRC, D_DIM, GATE_K, g_gw_h, K1)

        // epilogue: z = acc + gb; g = sigmoid(z); fused = g*tf + (1-g)*xf
#pragma unroll
        for (int mi = 0; mi < 4; mi++) {
#pragma unroll
            for (int half = 0; half < 2; half++) {
                const int m = m0 + wm * 64 + mi * 16 + qrow + half * 8;
                const __half* trow = g_tf_h + (size_t)m * D_DIM;
                const __half* xrow = g_xf_h + (size_t)m * D_DIM;
                __half* frow = g_fused + (size_t)m * D_DIM;
#pragma unroll
                for (int ni = 0; ni < 8; ni++) {
                    const int n = n0 + wn * 64 + ni * 8 + 2 * qk;
                    const float c0 = acc[mi][ni][half * 2 + 0];
                    const float c1 = acc[mi][ni][half * 2 + 1];
                    const float2 gbv = *reinterpret_cast<const float2*>(&gb[n]);
                    const float2 tv = __half22float2(*reinterpret_cast<const __half2*>(&trow[n]));
                    const float2 xv = __half22float2(*reinterpret_cast<const __half2*>(&xrow[n]));
                    const float g0 = 1.f / (1.f + __expf(-(c0 + gbv.x)));
                    const float g1 = 1.f / (1.f + __expf(-(c1 + gbv.y)));
                    const float f0 = g0 * tv.x + (1.f - g0) * xv.x;
                    const float f1 = g1 * tv.y + (1.f - g1) * xv.y;
                    *reinterpret_cast<__half2*>(&frow[n]) = __floats2half2_rn(f0, f1);
                }
            }
        }
        // publish: all threads' stores -> fence -> one release-increment
        __syncthreads();
        __threadfence();
        __syncthreads();
        if (tid == 0) atomicAdd(&g_flags[mb], 1);
    } else {
        // ---------------- out tile ----------------
        const int obid = bid - GATE_CTAS;
        const int mb = obid / NBLOCKS;
        const int m0 = mb * BM;
        const int n0 = (obid % NBLOCKS) * BN;

        if (threadIdx.x == 0) {
            volatile int* fl = g_flags + mb;
            while (*fl < NBLOCKS) __nanosleep(200);
        }
        __syncthreads();
        __threadfence();  // acquire: order g_fused reads after flag observation

        GEMM_PREAMBLE_VARS
        GEMM_MAINLOOP(D_DIM / BK, ID_SRC, D_DIM, ID_K, g_ow_h, D_DIM)

#pragma unroll
        for (int mi = 0; mi < 4; mi++) {
#pragma unroll
            for (int half = 0; half < 2; half++) {
                const int m = m0 + wm * 64 + mi * 16 + qrow + half * 8;
                float* orow = out + (size_t)m * D_DIM;
#pragma unroll
                for (int ni = 0; ni < 8; ni++) {
                    const int n = n0 + wn * 64 + ni * 8 + 2 * qk;
                    const float2 obv = *reinterpret_cast<const float2*>(&ob[n]);
                    float2 o;
                    o.x = acc[mi][ni][half * 2 + 0] + obv.x;
                    o.y = acc[mi][ni][half * 2 + 1] + obv.y;
                    *reinterpret_cast<float2*>(&orow[n]) = o;
                }
            }
        }
    }
}

extern "C" void kernel_launch(void* const* d_in, const int* in_sizes, int n_in,
                              void* d_out, int out_size) {
    const float* tf = (const float*)d_in[0];   // time_feat [16,1024,896]
    const float* xf = (const float*)d_in[1];   // text_feat [16,1024,896]
    // d_in[2] = word (dead: softmax over singleton axis == 1)
    const float* gw = (const float*)d_in[3];   // gate_w [896, 1792]
    const float* gb = (const float*)d_in[4];   // gate_b [896]
    const float* ow = (const float*)d_in[5];   // out_w  [896, 896]
    const float* ob = (const float*)d_in[6];   // out_b  [896]
    float* out = (float*)d_out;                // [16,1024,896] fp32

    static bool attr_set = false;
    if (!attr_set) {
        cudaFuncSetAttribute(k_gatedfusion, cudaFuncAttributeMaxDynamicSharedMemorySize, SMEM_BYTES);
        attr_set = true;
    }

    k_f2h_all<<<2368, 256>>>(tf, xf, gw, ow);
    k_gatedfusion<<<2 * GATE_CTAS, THREADS, SMEM_BYTES>>>(gb, ob, out);
}

// round 15
// speedup vs baseline: 1.0396x; 1.0396x over previous
#include <cuda_runtime.h>
#include <cuda_fp16.h>
#include <cstdint>

// GatedFusion via mma.sync f16 (m16n8k16, fp32 accum).
// R15 = R14 merged kernel (64x64 warp tiles, 4 warps/CTA, 3-stage smem,
// flag-chained gate->out tiles) with staging switched from LDG+STS (two
// l1tex passes per byte) to cp.async.ca (ONE pass, L1-ALLOCATING so the
// co-resident CTA sharing the same A m-block still hits L1 — the .cg
// variant in R6/R8 destroyed that reuse). ncu R14: L1=72% > tensor=49%,
// so the staging double-pass is the binding resource.
// Live math (softmax over singleton axis == 1 -> word/topk branch dead):
//   gate  = sigmoid([time|text] @ gate_w^T + gate_b)   (M=16384, N=896, K=1792)
//   fused = gate*time + (1-gate)*text
//   out   = fused @ out_w^T + out_b                    (M=16384, N=896, K=896)

#define M_TOT 16384
#define D_DIM 896
#define K1    1792

#define BM 128
#define BN 128
#define BK 32
#define THREADS 128
#define STAGES 3
#define AB_OFF (STAGES * 512)                 // uint4 entries: B region offset
#define SMEM_BYTES (2 * STAGES * 512 * 16)    // 48 KB -> 2 CTAs/SM

#define MBLOCKS (M_TOT / BM)                  // 128
#define NBLOCKS (D_DIM / BN)                  // 7
#define GATE_CTAS (MBLOCKS * NBLOCKS)         // 896

static __device__ __half g_tf_h[(size_t)M_TOT * D_DIM];
static __device__ __half g_xf_h[(size_t)M_TOT * D_DIM];
static __device__ __half g_gw_h[(size_t)D_DIM * K1];
static __device__ __half g_ow_h[(size_t)D_DIM * D_DIM];
static __device__ __half g_fused[(size_t)M_TOT * D_DIM];
static __device__ int    g_flags[MBLOCKS];

// ---------------- small helpers ---------------------------------------------
__device__ __forceinline__ void ldm_x4(uint32_t* r, uint32_t addr) {
    asm volatile("ldmatrix.sync.aligned.m8n8.x4.shared.b16 {%0,%1,%2,%3}, [%4];"
                 : "=r"(r[0]), "=r"(r[1]), "=r"(r[2]), "=r"(r[3]) : "r"(addr));
}
__device__ __forceinline__ void mma_f16(float* c, const uint32_t* a, const uint32_t* b) {
    asm volatile(
        "mma.sync.aligned.m16n8k16.row.col.f32.f16.f16.f32 "
        "{%0,%1,%2,%3}, {%4,%5,%6,%7}, {%8,%9}, {%0,%1,%2,%3};"
        : "+f"(c[0]), "+f"(c[1]), "+f"(c[2]), "+f"(c[3])
        : "r"(a[0]), "r"(a[1]), "r"(a[2]), "r"(a[3]), "r"(b[0]), "r"(b[1]));
}
// L1-ALLOCATING async copy (NOT .cg: .cg bypasses L1 and kills cross-CTA
// A-tile reuse — the R6/R8 failure mode).
__device__ __forceinline__ void cp16(uint32_t dst, const void* src) {
    asm volatile("cp.async.ca.shared.global [%0], [%1], 16;" :: "r"(dst), "l"(src));
}
#define CP_COMMIT() asm volatile("cp.async.commit_group;" ::: "memory")
#define CP_WAIT(n)  asm volatile("cp.async.wait_group %0;" :: "n"(n) : "memory")

// ---------------- fused fp32 -> fp16 pre-convert + flag reset ----------------
#define N_ACT ((size_t)M_TOT * D_DIM)
#define N_GW  ((size_t)D_DIM * K1)
#define N_OW  ((size_t)D_DIM * D_DIM)
__global__ void k_f2h_all(const float* __restrict__ tf, const float* __restrict__ xf,
                          const float* __restrict__ gw, const float* __restrict__ ow) {
    if (blockIdx.x == 0 && threadIdx.x < MBLOCKS) g_flags[threadIdx.x] = 0;
    const size_t tot = (2 * N_ACT + N_GW + N_OW) / 4;
    for (size_t g = blockIdx.x * blockDim.x + threadIdx.x; g < tot;
         g += (size_t)gridDim.x * blockDim.x) {
        const float* src; __half* dst; size_t i = g * 4;
        if (i < N_ACT) {
            src = tf + i; dst = g_tf_h + i;
        } else if (i < 2 * N_ACT) {
            src = xf + (i - N_ACT); dst = g_xf_h + (i - N_ACT);
        } else if (i < 2 * N_ACT + N_GW) {
            src = gw + (i - 2 * N_ACT); dst = g_gw_h + (i - 2 * N_ACT);
        } else {
            src = ow + (i - 2 * N_ACT - N_GW); dst = g_ow_h + (i - 2 * N_ACT - N_GW);
        }
        float4 v = *reinterpret_cast<const float4*>(src);
        __half2 hh[2] = {__floats2half2_rn(v.x, v.y), __floats2half2_rn(v.z, v.w)};
        *reinterpret_cast<uint2*>(dst) = *reinterpret_cast<const uint2*>(hh);
    }
}

// ---------------- staging: cp.async.ca 16B -> swizzled shared ----------------
// Tile = 128 rows x 32 k (half) for A and B. 16B entries:
//   entry(slab,row) = slab*128 + (row ^ (slab*2)), slab = k8/8 in {0..3}
// 128 threads: row32 = tid>>2 (0..31), slab = tid&3; u<4 covers 128 rows.
__device__ __forceinline__ void issue_tile(uint32_t sbase, int stage,
                                           const __half* __restrict__ A, int ldA,
                                           int m0, int kA,
                                           const __half* __restrict__ B, int ldB,
                                           int n0, int kB, int row32, int slab) {
    const uint32_t boff = (uint32_t)AB_OFF * 16;
#pragma unroll
    for (int u = 0; u < 4; u++) {
        const int row = row32 + u * 32;
        const uint32_t e = (uint32_t)(stage * 512 + slab * 128 + (row ^ (slab * 2))) * 16;
        cp16(sbase + e, &A[(size_t)(m0 + row) * ldA + kA + slab * 8]);
        cp16(sbase + boff + e, &B[(size_t)(n0 + row) * ldB + kB + slab * 8]);
    }
}

// ---------------- compute: warp tile 64x64, mi=4 x ni=8, m16n8k16 ------------
#define GEMM_COMPUTE(cur)                                                         \
    _Pragma("unroll")                                                             \
    for (int ks = 0; ks < 2; ks++) {                                              \
        uint32_t af[4][4], bf[8][2];                                              \
        _Pragma("unroll")                                                         \
        for (int mi = 0; mi < 4; mi++) {                                          \
            const int slab = ks * 2 + a_kh;                                       \
            const int row = wm * 64 + mi * 16 + a_row;                            \
            ldm_x4(af[mi], sbase +                                                \
                   (uint32_t)((cur) * 512 + slab * 128 + (row ^ (slab * 2))) * 16); \
        }                                                                         \
        _Pragma("unroll")                                                         \
        for (int np = 0; np < 4; np++) {                                          \
            const int slab = ks * 2 + b_kh;                                       \
            const int nrow = wn * 64 + np * 16 + b_row;                           \
            uint32_t t[4];                                                        \
            ldm_x4(t, sbase + (uint32_t)AB_OFF * 16 +                             \
                   (uint32_t)((cur) * 512 + slab * 128 + (nrow ^ (slab * 2))) * 16); \
            bf[np * 2][0] = t[0]; bf[np * 2][1] = t[1];                           \
            bf[np * 2 + 1][0] = t[2]; bf[np * 2 + 1][1] = t[3];                   \
        }                                                                         \
        _Pragma("unroll")                                                         \
        for (int mi = 0; mi < 4; mi++)                                            \
            _Pragma("unroll")                                                     \
            for (int ni = 0; ni < 8; ni++)                                        \
                mma_f16(acc[mi][ni], af[mi], bf[ni]);                             \
    }

#define GEMM_PREAMBLE_VARS                                                        \
    const uint32_t sbase = (uint32_t)__cvta_generic_to_shared(smem_dyn);          \
    const int tid  = threadIdx.x;                                                 \
    const int wid  = tid >> 5;                                                    \
    const int lane = tid & 31;                                                    \
    const int qrow = lane >> 2;                                                   \
    const int qk   = lane & 3;                                                    \
    const int wm   = wid & 1;                                                     \
    const int wn   = wid >> 1;                                                    \
    const int row32 = tid >> 2;                                                   \
    const int slabL = tid & 3;                                                    \
    const int a_row = lane & 15;                                                  \
    const int a_kh  = lane >> 4;                                                  \
    const int b_row = (lane & 7) + ((lane >> 4) << 3);                            \
    const int b_kh  = (lane >> 3) & 1;                                            \
    float acc[4][8][4];                                                           \
    _Pragma("unroll")                                                             \
    for (int mi = 0; mi < 4; mi++)                                                \
        _Pragma("unroll")                                                         \
        for (int ni = 0; ni < 8; ni++)                                            \
            _Pragma("unroll")                                                     \
            for (int t = 0; t < 4; t++) acc[mi][ni][t] = 0.f;

// cp.async 3-stage pipeline, one sync per tile.
//   iter kt: wait_group(1)  -> tile kt's bytes landed (this thread's groups);
//            __syncthreads  -> publishes ALL threads' landed groups AND orders
//                              compute(kt-1) before the slot-(kt-1)%3 refill;
//            issue(kt+2) into slot (kt+2)%3 == (kt-1)%3; commit (every iter,
//            empty groups keep the wait accounting aligned);
//            compute(kt) from slot kt%3.
// Steady state: 2 tiles in flight (kt+1, kt+2) while computing kt = 3 slots.
#define GEMM_MAINLOOP(NT, SRC_A, LD_A, K_A, SRC_B, LD_B)                          \
    {                                                                             \
        issue_tile(sbase, 0, SRC_A(0), LD_A, m0, K_A(0), SRC_B, LD_B, n0, 0, row32, slabL); \
        CP_COMMIT();                                                              \
        issue_tile(sbase, 1, SRC_A(BK), LD_A, m0, K_A(BK), SRC_B, LD_B, n0, BK, row32, slabL); \
        CP_COMMIT();                                                              \
        for (int kt = 0; kt < (NT); kt++) {                                       \
            CP_WAIT(1);                                                           \
            __syncthreads();                                                      \
            const int kn = kt + 2;                                                \
            if (kn < (NT)) {                                                      \
                const int kb = kn * BK;                                           \
                issue_tile(sbase, kn % STAGES, SRC_A(kb), LD_A, m0, K_A(kb),      \
                           SRC_B, LD_B, n0, kb, row32, slabL);                    \
            }                                                                     \
            CP_COMMIT();                                                          \
            GEMM_COMPUTE(kt % STAGES)                                             \
        }                                                                         \
    }

#define GATE_SRC(kb) ((kb) < D_DIM ? g_tf_h : g_xf_h)
#define GATE_K(kb)   ((kb) < D_DIM ? (kb) : (kb) - D_DIM)
#define ID_SRC(kb)   (g_fused)
#define ID_K(kb)     (kb)

// ============================================================================
// Merged kernel: bids [0,896) gate tiles; bids [896,1792) out tiles that
// spin on g_flags[mblock] (7 gate n-tiles per m-block) before their mainloop.
// CTA slots are granted in bid order -> all gate CTAs issue before any out
// CTA -> no deadlock; out CTAs fill the gate grid's tail-wave idle slots.
// ============================================================================
__global__ void __launch_bounds__(THREADS, 2)
k_gatedfusion(const float* __restrict__ gb, const float* __restrict__ ob,
              float* __restrict__ out)
{
    extern __shared__ uint4 smem_dyn[];
    const int bid = blockIdx.x;

    if (bid < GATE_CTAS) {
        // ---------------- gate tile ----------------
        const int mb = bid / NBLOCKS;
        const int m0 = mb * BM;
        const int n0 = (bid % NBLOCKS) * BN;
        GEMM_PREAMBLE_VARS
        GEMM_MAINLOOP(K1 / BK, GATE_SRC, D_DIM, GATE_K, g_gw_h, K1)

        // epilogue: z = acc + gb; g = sigmoid(z); fused = g*tf + (1-g)*xf
#pragma unroll
        for (int mi = 0; mi < 4; mi++) {
#pragma unroll
            for (int half = 0; half < 2; half++) {
                const int m = m0 + wm * 64 + mi * 16 + qrow + half * 8;
                const __half* trow = g_tf_h + (size_t)m * D_DIM;
                const __half* xrow = g_xf_h + (size_t)m * D_DIM;
                __half* frow = g_fused + (size_t)m * D_DIM;
#pragma unroll
                for (int ni = 0; ni < 8; ni++) {
                    const int n = n0 + wn * 64 + ni * 8 + 2 * qk;
                    const float c0 = acc[mi][ni][half * 2 + 0];
                    const float c1 = acc[mi][ni][half * 2 + 1];
                    const float2 gbv = *reinterpret_cast<const float2*>(&gb[n]);
                    const float2 tv = __half22float2(*reinterpret_cast<const __half2*>(&trow[n]));
                    const float2 xv = __half22float2(*reinterpret_cast<const __half2*>(&xrow[n]));
                    const float g0 = 1.f / (1.f + __expf(-(c0 + gbv.x)));
                    const float g1 = 1.f / (1.f + __expf(-(c1 + gbv.y)));
                    const float f0 = g0 * tv.x + (1.f - g0) * xv.x;
                    const float f1 = g1 * tv.y + (1.f - g1) * xv.y;
                    *reinterpret_cast<__half2*>(&frow[n]) = __floats2half2_rn(f0, f1);
                }
            }
        }
        // publish: all threads' stores -> fence -> one release-increment
        __syncthreads();
        __threadfence();
        __syncthreads();
        if (tid == 0) atomicAdd(&g_flags[mb], 1);
    } else {
        // ---------------- out tile ----------------
        const int obid = bid - GATE_CTAS;
        const int mb = obid / NBLOCKS;
        const int m0 = mb * BM;
        const int n0 = (obid % NBLOCKS) * BN;

        if (threadIdx.x == 0) {
            volatile int* fl = g_flags + mb;
            while (*fl < NBLOCKS) __nanosleep(200);
        }
        __syncthreads();
        __threadfence();  // acquire: order g_fused reads after flag observation

        GEMM_PREAMBLE_VARS
        GEMM_MAINLOOP(D_DIM / BK, ID_SRC, D_DIM, ID_K, g_ow_h, D_DIM)

#pragma unroll
        for (int mi = 0; mi < 4; mi++) {
#pragma unroll
            for (int half = 0; half < 2; half++) {
                const int m = m0 + wm * 64 + mi * 16 + qrow + half * 8;
                float* orow = out + (size_t)m * D_DIM;
#pragma unroll
                for (int ni = 0; ni < 8; ni++) {
                    const int n = n0 + wn * 64 + ni * 8 + 2 * qk;
                    const float2 obv = *reinterpret_cast<const float2*>(&ob[n]);
                    float2 o;
                    o.x = acc[mi][ni][half * 2 + 0] + obv.x;
                    o.y = acc[mi][ni][half * 2 + 1] + obv.y;
                    *reinterpret_cast<float2*>(&orow[n]) = o;
                }
            }
        }
    }
}

extern "C" void kernel_launch(void* const* d_in, const int* in_sizes, int n_in,
                              void* d_out, int out_size) {
    const float* tf = (const float*)d_in[0];   // time_feat [16,1024,896]
    const float* xf = (const float*)d_in[1];   // text_feat [16,1024,896]
    // d_in[2] = word (dead: softmax over singleton axis == 1)
    const float* gw = (const float*)d_in[3];   // gate_w [896, 1792]
    const float* gb = (const float*)d_in[4];   // gate_b [896]
    const float* ow = (const float*)d_in[5];   // out_w  [896, 896]
    const float* ob = (const float*)d_in[6];   // out_b  [896]
    float* out = (float*)d_out;                // [16,1024,896] fp32

    static bool attr_set = false;
    if (!attr_set) {
        cudaFuncSetAttribute(k_gatedfusion, cudaFuncAttributeMaxDynamicSharedMemorySize, SMEM_BYTES);
        attr_set = true;
    }

    k_f2h_all<<<2368, 256>>>(tf, xf, gw, ow);
    k_gatedfusion<<<2 * GATE_CTAS, THREADS, SMEM_BYTES>>>(gb, ob, out);
}

// round 17
// speedup vs baseline: 1.0461x; 1.0062x over previous
#include <cuda_runtime.h>
#include <cuda_fp16.h>
#include <cstdint>

// GatedFusion via mma.sync f16 (m16n8k16, fp32 accum).
// R16 = R15 champion (merged gate->out kernel, cp.async.ca 3-stage staging,
// 64x64 warp tiles) with GEMM_COMPUTE restructured: ALL 16 ldmatrix.x4 for
// the tile issued up front (double fragment buffer, +24 regs), then one
// uninterrupted 64-MMA burst. With 2 warps/SMSP, long MMA bursts let the
// co-resident warp's LDSM phase hide completely (R15: tensor=51%, the pipe
// idled while both warps were in LDSM).
// Live math (softmax over singleton axis == 1 -> word/topk branch dead):
//   gate  = sigmoid([time|text] @ gate_w^T + gate_b)   (M=16384, N=896, K=1792)
//   fused = gate*time + (1-gate)*text
//   out   = fused @ out_w^T + out_b                    (M=16384, N=896, K=896)

#define M_TOT 16384
#define D_DIM 896
#define K1    1792

#define BM 128
#define BN 128
#define BK 32
#define THREADS 128
#define STAGES 3
#define AB_OFF (STAGES * 512)                 // uint4 entries: B region offset
#define SMEM_BYTES (2 * STAGES * 512 * 16)    // 48 KB -> 2 CTAs/SM

#define MBLOCKS (M_TOT / BM)                  // 128
#define NBLOCKS (D_DIM / BN)                  // 7
#define GATE_CTAS (MBLOCKS * NBLOCKS)         // 896

static __device__ __half g_tf_h[(size_t)M_TOT * D_DIM];
static __device__ __half g_xf_h[(size_t)M_TOT * D_DIM];
static __device__ __half g_gw_h[(size_t)D_DIM * K1];
static __device__ __half g_ow_h[(size_t)D_DIM * D_DIM];
static __device__ __half g_fused[(size_t)M_TOT * D_DIM];
static __device__ int    g_flags[MBLOCKS];

// ---------------- small helpers ---------------------------------------------
__device__ __forceinline__ void ldm_x4(uint32_t* r, uint32_t addr) {
    asm volatile("ldmatrix.sync.aligned.m8n8.x4.shared.b16 {%0,%1,%2,%3}, [%4];"
                 : "=r"(r[0]), "=r"(r[1]), "=r"(r[2]), "=r"(r[3]) : "r"(addr));
}
__device__ __forceinline__ void mma_f16(float* c, const uint32_t* a, const uint32_t* b) {
    asm volatile(
        "mma.sync.aligned.m16n8k16.row.col.f32.f16.f16.f32 "
        "{%0,%1,%2,%3}, {%4,%5,%6,%7}, {%8,%9}, {%0,%1,%2,%3};"
        : "+f"(c[0]), "+f"(c[1]), "+f"(c[2]), "+f"(c[3])
        : "r"(a[0]), "r"(a[1]), "r"(a[2]), "r"(a[3]), "r"(b[0]), "r"(b[1]));
}
// L1-ALLOCATING async copy (NOT .cg: .cg bypasses L1 and kills cross-CTA
// A-tile reuse — the R6/R8 failure mode).
__device__ __forceinline__ void cp16(uint32_t dst, const void* src) {
    asm volatile("cp.async.ca.shared.global [%0], [%1], 16;" :: "r"(dst), "l"(src));
}
#define CP_COMMIT() asm volatile("cp.async.commit_group;" ::: "memory")
#define CP_WAIT(n)  asm volatile("cp.async.wait_group %0;" :: "n"(n) : "memory")

// ---------------- fused fp32 -> fp16 pre-convert + flag reset ----------------
#define N_ACT ((size_t)M_TOT * D_DIM)
#define N_GW  ((size_t)D_DIM * K1)
#define N_OW  ((size_t)D_DIM * D_DIM)
__global__ void k_f2h_all(const float* __restrict__ tf, const float* __restrict__ xf,
                          const float* __restrict__ gw, const float* __restrict__ ow) {
    if (blockIdx.x == 0 && threadIdx.x < MBLOCKS) g_flags[threadIdx.x] = 0;
    const size_t tot = (2 * N_ACT + N_GW + N_OW) / 4;
    for (size_t g = blockIdx.x * blockDim.x + threadIdx.x; g < tot;
         g += (size_t)gridDim.x * blockDim.x) {
        const float* src; __half* dst; size_t i = g * 4;
        if (i < N_ACT) {
            src = tf + i; dst = g_tf_h + i;
        } else if (i < 2 * N_ACT) {
            src = xf + (i - N_ACT); dst = g_xf_h + (i - N_ACT);
        } else if (i < 2 * N_ACT + N_GW) {
            src = gw + (i - 2 * N_ACT); dst = g_gw_h + (i - 2 * N_ACT);
        } else {
            src = ow + (i - 2 * N_ACT - N_GW); dst = g_ow_h + (i - 2 * N_ACT - N_GW);
        }
        float4 v = *reinterpret_cast<const float4*>(src);
        __half2 hh[2] = {__floats2half2_rn(v.x, v.y), __floats2half2_rn(v.z, v.w)};
        *reinterpret_cast<uint2*>(dst) = *reinterpret_cast<const uint2*>(hh);
    }
}

// ---------------- staging: cp.async.ca 16B -> swizzled shared ----------------
// Tile = 128 rows x 32 k (half) for A and B. 16B entries:
//   entry(slab,row) = slab*128 + (row ^ (slab*2)), slab = k8/8 in {0..3}
// 128 threads: row32 = tid>>2 (0..31), slab = tid&3; u<4 covers 128 rows.
__device__ __forceinline__ void issue_tile(uint32_t sbase, int stage,
                                           const __half* __restrict__ A, int ldA,
                                           int m0, int kA,
                                           const __half* __restrict__ B, int ldB,
                                           int n0, int kB, int row32, int slab) {
    const uint32_t boff = (uint32_t)AB_OFF * 16;
#pragma unroll
    for (int u = 0; u < 4; u++) {
        const int row = row32 + u * 32;
        const uint32_t e = (uint32_t)(stage * 512 + slab * 128 + (row ^ (slab * 2))) * 16;
        cp16(sbase + e, &A[(size_t)(m0 + row) * ldA + kA + slab * 8]);
        cp16(sbase + boff + e, &B[(size_t)(n0 + row) * ldB + kB + slab * 8]);
    }
}

// ---------------- compute: warp tile 64x64, mi=4 x ni=8, m16n8k16 ------------
// ALL fragment loads first (16 ldm_x4, independent, LSU-pipelined), then one
// 64-MMA burst: keeps the tensor pipe busy in long stretches so the other
// warp on the same SMSP hides its LDSM phase under our burst.
#define GEMM_COMPUTE(cur)                                                         \
    {                                                                             \
        uint32_t af[2][4][4], bf[2][8][2];                                        \
        _Pragma("unroll")                                                         \
        for (int ks = 0; ks < 2; ks++) {                                          \
            _Pragma("unroll")                                                     \
            for (int mi = 0; mi < 4; mi++) {                                      \
                const int slab = ks * 2 + a_kh;                                   \
                const int row = wm * 64 + mi * 16 + a_row;                        \
                ldm_x4(af[ks][mi], sbase +                                        \
                       (uint32_t)((cur) * 512 + slab * 128 + (row ^ (slab * 2))) * 16); \
            }                                                                     \
            _Pragma("unroll")                                                     \
            for (int np = 0; np < 4; np++) {                                      \
                const int slab = ks * 2 + b_kh;                                   \
                const int nrow = wn * 64 + np * 16 + b_row;                       \
                uint32_t t[4];                                                    \
                ldm_x4(t, sbase + (uint32_t)AB_OFF * 16 +                         \
                       (uint32_t)((cur) * 512 + slab * 128 + (nrow ^ (slab * 2))) * 16); \
                bf[ks][np * 2][0] = t[0]; bf[ks][np * 2][1] = t[1];               \
                bf[ks][np * 2 + 1][0] = t[2]; bf[ks][np * 2 + 1][1] = t[3];       \
            }                                                                     \
        }                                                                         \
        _Pragma("unroll")                                                         \
        for (int ks = 0; ks < 2; ks++)                                            \
            _Pragma("unroll")                                                     \
            for (int mi = 0; mi < 4; mi++)                                        \
                _Pragma("unroll")                                                 \
                for (int ni = 0; ni < 8; ni++)                                    \
                    mma_f16(acc[mi][ni], af[ks][mi], bf[ks][ni]);                 \
    }

#define GEMM_PREAMBLE_VARS                                                        \
    const uint32_t sbase = (uint32_t)__cvta_generic_to_shared(smem_dyn);          \
    const int tid  = threadIdx.x;                                                 \
    const int wid  = tid >> 5;                                                    \
    const int lane = tid & 31;                                                    \
    const int qrow = lane >> 2;                                                   \
    const int qk   = lane & 3;                                                    \
    const int wm   = wid & 1;                                                     \
    const int wn   = wid >> 1;                                                    \
    const int row32 = tid >> 2;                                                   \
    const int slabL = tid & 3;                                                    \
    const int a_row = lane & 15;                                                  \
    const int a_kh  = lane >> 4;                                                  \
    const int b_row = (lane & 7) + ((lane >> 4) << 3);                            \
    const int b_kh  = (lane >> 3) & 1;                                            \
    float acc[4][8][4];                                                           \
    _Pragma("unroll")                                                             \
    for (int mi = 0; mi < 4; mi++)                                                \
        _Pragma("unroll")                                                         \
        for (int ni = 0; ni < 8; ni++)                                            \
            _Pragma("unroll")                                                     \
            for (int t = 0; t < 4; t++) acc[mi][ni][t] = 0.f;

// cp.async 3-stage pipeline, one sync per tile (R15 ordering).
#define GEMM_MAINLOOP(NT, SRC_A, LD_A, K_A, SRC_B, LD_B)                          \
    {                                                                             \
        issue_tile(sbase, 0, SRC_A(0), LD_A, m0, K_A(0), SRC_B, LD_B, n0, 0, row32, slabL); \
        CP_COMMIT();                                                              \
        issue_tile(sbase, 1, SRC_A(BK), LD_A, m0, K_A(BK), SRC_B, LD_B, n0, BK, row32, slabL); \
        CP_COMMIT();                                                              \
        for (int kt = 0; kt < (NT); kt++) {                                       \
            CP_WAIT(1);                                                           \
            __syncthreads();                                                      \
            const int kn = kt + 2;                                                \
            if (kn < (NT)) {                                                      \
                const int kb = kn * BK;                                           \
                issue_tile(sbase, kn % STAGES, SRC_A(kb), LD_A, m0, K_A(kb),      \
                           SRC_B, LD_B, n0, kb, row32, slabL);                    \
            }                                                                     \
            CP_COMMIT();                                                          \
            GEMM_COMPUTE(kt % STAGES)                                             \
        }                                                                         \
    }

#define GATE_SRC(kb) ((kb) < D_DIM ? g_tf_h : g_xf_h)
#define GATE_K(kb)   ((kb) < D_DIM ? (kb) : (kb) - D_DIM)
#define ID_SRC(kb)   (g_fused)
#define ID_K(kb)     (kb)

// ============================================================================
// Merged kernel: bids [0,896) gate tiles; bids [896,1792) out tiles that
// spin on g_flags[mblock] (7 gate n-tiles per m-block) before their mainloop.
// CTA slots are granted in bid order -> all gate CTAs issue before any out
// CTA -> no deadlock; out CTAs fill the gate grid's tail-wave idle slots.
// ============================================================================
__global__ void __launch_bounds__(THREADS, 2)
k_gatedfusion(const float* __restrict__ gb, const float* __restrict__ ob,
              float* __restrict__ out)
{
    extern __shared__ uint4 smem_dyn[];
    const int bid = blockIdx.x;

    if (bid < GATE_CTAS) {
        // ---------------- gate tile ----------------
        const int mb = bid / NBLOCKS;
        const int m0 = mb * BM;
        const int n0 = (bid % NBLOCKS) * BN;
        GEMM_PREAMBLE_VARS
        GEMM_MAINLOOP(K1 / BK, GATE_SRC, D_DIM, GATE_K, g_gw_h, K1)

        // epilogue: z = acc + gb; g = sigmoid(z); fused = g*tf + (1-g)*xf
#pragma unroll
        for (int mi = 0; mi < 4; mi++) {
#pragma unroll
            for (int half = 0; half < 2; half++) {
                const int m = m0 + wm * 64 + mi * 16 + qrow + half * 8;
                const __half* trow = g_tf_h + (size_t)m * D_DIM;
                const __half* xrow = g_xf_h + (size_t)m * D_DIM;
                __half* frow = g_fused + (size_t)m * D_DIM;
#pragma unroll
                for (int ni = 0; ni < 8; ni++) {
                    const int n = n0 + wn * 64 + ni * 8 + 2 * qk;
                    const float c0 = acc[mi][ni][half * 2 + 0];
                    const float c1 = acc[mi][ni][half * 2 + 1];
                    const float2 gbv = *reinterpret_cast<const float2*>(&gb[n]);
                    const float2 tv = __half22float2(*reinterpret_cast<const __half2*>(&trow[n]));
                    const float2 xv = __half22float2(*reinterpret_cast<const __half2*>(&xrow[n]));
                    const float g0 = 1.f / (1.f + __expf(-(c0 + gbv.x)));
                    const float g1 = 1.f / (1.f + __expf(-(c1 + gbv.y)));
                    const float f0 = g0 * tv.x + (1.f - g0) * xv.x;
                    const float f1 = g1 * tv.y + (1.f - g1) * xv.y;
                    *reinterpret_cast<__half2*>(&frow[n]) = __floats2half2_rn(f0, f1);
                }
            }
        }
        // publish: all threads' stores -> fence -> one release-increment
        __syncthreads();
        __threadfence();
        __syncthreads();
        if (tid == 0) atomicAdd(&g_flags[mb], 1);
    } else {
        // ---------------- out tile ----------------
        const int obid = bid - GATE_CTAS;
        const int mb = obid / NBLOCKS;
        const int m0 = mb * BM;
        const int n0 = (obid % NBLOCKS) * BN;

        if (threadIdx.x == 0) {
            volatile int* fl = g_flags + mb;
            while (*fl < NBLOCKS) __nanosleep(200);
        }
        __syncthreads();
        __threadfence();  // acquire: order g_fused reads after flag observation

        GEMM_PREAMBLE_VARS
        GEMM_MAINLOOP(D_DIM / BK, ID_SRC, D_DIM, ID_K, g_ow_h, D_DIM)

#pragma unroll
        for (int mi = 0; mi < 4; mi++) {
#pragma unroll
            for (int half = 0; half < 2; half++) {
                const int m = m0 + wm * 64 + mi * 16 + qrow + half * 8;
                float* orow = out + (size_t)m * D_DIM;
#pragma unroll
                for (int ni = 0; ni < 8; ni++) {
                    const int n = n0 + wn * 64 + ni * 8 + 2 * qk;
                    const float2 obv = *reinterpret_cast<const float2*>(&ob[n]);
                    float2 o;
                    o.x = acc[mi][ni][half * 2 + 0] + obv.x;
                    o.y = acc[mi][ni][half * 2 + 1] + obv.y;
                    *reinterpret_cast<float2*>(&orow[n]) = o;
                }
            }
        }
    }
}

extern "C" void kernel_launch(void* const* d_in, const int* in_sizes, int n_in,
                              void* d_out, int out_size) {
    const float* tf = (const float*)d_in[0];   // time_feat [16,1024,896]
    const float* xf = (const float*)d_in[1];   // text_feat [16,1024,896]
    // d_in[2] = word (dead: softmax over singleton axis == 1)
    const float* gw = (const float*)d_in[3];   // gate_w [896, 1792]
    const float* gb = (const float*)d_in[4];   // gate_b [896]
    const float* ow = (const float*)d_in[5];   // out_w  [896, 896]
    const float* ob = (const float*)d_in[6];   // out_b  [896]
    float* out = (float*)d_out;                // [16,1024,896] fp32

    static bool attr_set = false;
    if (!attr_set) {
        cudaFuncSetAttribute(k_gatedfusion, cudaFuncAttributeMaxDynamicSharedMemorySize, SMEM_BYTES);
        attr_set = true;
    }

    k_f2h_all<<<2368, 256>>>(tf, xf, gw, ow);
    k_gatedfusion<<<2 * GATE_CTAS, THREADS, SMEM_BYTES>>>(gb, ob, out);
}